// round 16
// baseline (speedup 1.0000x reference)
#include <cuda_runtime.h>

// Fixed problem shapes
#define BB 64
#define CC 64   // C == Co
#define TT 32
#define NN 64
#define KK 3

// 3 buffers, stride 64 (all accesses are row-contiguous or broadcast)
#define SX_OFF  0               // x -> yT
#define SW_OFF  4096            // WT
#define SAS_OFF 8192            // Asum
#define SD_OFF  12288           // dinv 3x64
#define SMEM_FLOATS (12288 + 3 * 64)
#define SMEM_BYTES  (SMEM_FLOATS * 4)     // 49,920 B -> 4 CTAs/SM

// W transposed once into device-global scratch (WT[c][o] = W[o][c])
__device__ float g_WT[CC * CC];

__global__ void wt_transpose_kernel(const float* __restrict__ W)
{
    const int i = blockIdx.x * 256 + threadIdx.x;   // 0..4095
    g_WT[(i & 63) * CC + (i >> 6)] = W[i];
}

#define BARX(id) asm volatile("bar.sync %0, 128;" :: "r"(id) : "memory")

// One CTA per (b, t). 256 threads = GEMM half (warps 0-3) + A half (warps 4-7).
__global__ void __launch_bounds__(256, 4)
ctg_kernel(const float* __restrict__ x,
           const float* __restrict__ A,
           const float* __restrict__ bias,
           float* __restrict__ out,
           int copyA)
{
    extern __shared__ float sm[];
    float* sX  = sm + SX_OFF;
    float* sW  = sm + SW_OFF;
    float* sAs = sm + SAS_OFF;
    float* sD  = sm + SD_OFF;

    const int tid = threadIdx.x;
    const int b   = blockIdx.x / TT;
    const int t   = blockIdx.x % TT;

    if (tid < 128) {
        // ================= GEMM half: stage + GEMM1 (8x4 tiles) =================
        const int lt = tid;
        const int tx = lt & 15;    // 4-col group (o)
        const int ty = lt >> 4;    // 8-row group (n)

        #pragma unroll
        for (int it = 0; it < 8; it++) {
            const int e4 = it * 128 + lt;    // float4 slot 0..1023
            const int r  = e4 >> 4;
            const int c4 = e4 & 15;
            *(float4*)(sX + r * NN + c4 * 4) =
                *(const float4*)(x + (((size_t)(b * CC + r) * TT + t) * NN) + c4 * 4);
            *(float4*)(sW + r * NN + c4 * 4) =
                *(const float4*)(g_WT + (size_t)e4 * 4);
        }
        BARX(1);

        // GEMM1: yT[n][o] = sum_c x[c][n] * WT[c][o] + bias[o]
        float acc[8][4];
        {
            const float4 bia = *(const float4*)(bias + tx * 4);
            #pragma unroll
            for (int i = 0; i < 8; i++) {
                acc[i][0] = bia.x; acc[i][1] = bia.y; acc[i][2] = bia.z; acc[i][3] = bia.w;
            }
        }
        #pragma unroll 4
        for (int kk = 0; kk < 64; kk++) {
            const float4 a0 = *(const float4*)(sX + kk * NN + ty * 8);      // x[kk][8ty..]
            const float4 a1 = *(const float4*)(sX + kk * NN + ty * 8 + 4);
            const float4 bv = *(const float4*)(sW + kk * NN + tx * 4);      // WT[kk][4tx..]
            const float av[8] = {a0.x, a0.y, a0.z, a0.w, a1.x, a1.y, a1.z, a1.w};
            #pragma unroll
            for (int i = 0; i < 8; i++) {
                acc[i][0] += av[i] * bv.x;
                acc[i][1] += av[i] * bv.y;
                acc[i][2] += av[i] * bv.z;
                acc[i][3] += av[i] * bv.w;
            }
        }
        BARX(1);    // all sX reads done before overwrite

        #pragma unroll
        for (int i = 0; i < 8; i++) {
            float4 r4;
            r4.x = acc[i][0]; r4.y = acc[i][1]; r4.z = acc[i][2]; r4.w = acc[i][3];
            *(float4*)(sX + (8 * ty + i) * NN + tx * 4) = r4;    // yT[n][o]
        }
    } else {
        // ================= A half: copy-out + degrees + Asum =================
        const int lt  = tid - 128;
        const int txg = lt & 15;
        const int tyg = lt >> 4;          // 0..7
        const int m0  = txg * 4;
        float* outA = out + (size_t)BB * CC * TT * NN;

        float4 asum[8];
        #pragma unroll
        for (int it = 0; it < 8; it++) asum[it] = make_float4(0.f, 0.f, 0.f, 0.f);

        #pragma unroll
        for (int k = 0; k < KK; k++) {
            const size_t base = (((size_t)b * KK + k) * TT + t) * (size_t)(NN * NN);
            float* sDk = sD + k * 64;

            float4 a[8];
            #pragma unroll
            for (int it = 0; it < 8; it++) {
                const int e4 = it * 128 + lt;
                a[it] = *(const float4*)(A + base + (size_t)e4 * 4);
                if (copyA) *(float4*)(outA + base + (size_t)e4 * 4) = a[it];
            }

            // row degrees: row n = it*8 + tyg spans the 16 lanes sharing tyg
            #pragma unroll
            for (int it = 0; it < 8; it++) {
                float s = a[it].x + a[it].y + a[it].z + a[it].w;
                s += __shfl_xor_sync(0xffffffffu, s, 1);
                s += __shfl_xor_sync(0xffffffffu, s, 2);
                s += __shfl_xor_sync(0xffffffffu, s, 4);
                s += __shfl_xor_sync(0xffffffffu, s, 8);
                if (txg == 0) sDk[it * 8 + tyg] = rsqrtf(s + 1.0f);   // A_tilde = A + I
            }
            BARX(2);

            const float4 dm = *(const float4*)(sDk + m0);
            #pragma unroll
            for (int it = 0; it < 8; it++) {
                const int n = it * 8 + tyg;
                const float dn = sDk[n];
                float4 v = a[it];
                const int d = n - m0;
                if (d == 0) v.x += 1.0f;
                if (d == 1) v.y += 1.0f;
                if (d == 2) v.z += 1.0f;
                if (d == 3) v.w += 1.0f;
                asum[it].x += v.x * dn * dm.x;
                asum[it].y += v.y * dn * dm.y;
                asum[it].z += v.z * dn * dm.z;
                asum[it].w += v.w * dn * dm.w;
            }
            // no trailing bar: next k writes a different sD slab
        }

        #pragma unroll
        for (int it = 0; it < 8; it++)
            *(float4*)(sAs + (it * 8 + tyg) * NN + m0) = asum[it];
    }

    __syncthreads();   // join: yT (sX) and Asum (sAs) visible to all

    // ---- GEMM2 (all 256 threads, 4x4 tiles): x_out[c][m] = sum_n yT[n][c]*Asum[n][m]
    const int tx2 = tid & 15;
    const int ty2 = tid >> 4;
    const int m0b = tx2 * 4;

    float acc2[4][4];
    #pragma unroll
    for (int i = 0; i < 4; i++)
        #pragma unroll
        for (int j = 0; j < 4; j++) acc2[i][j] = 0.0f;

    #pragma unroll 8
    for (int kk = 0; kk < 64; kk++) {
        const float4 av = *(const float4*)(sX  + kk * NN + ty2 * 4);  // yT[kk][4ty2..]
        const float4 bv = *(const float4*)(sAs + kk * NN + m0b);      // Asum[kk][4tx2..]
        const float a0 = av.x, a1 = av.y, a2 = av.z, a3 = av.w;
        acc2[0][0] += a0 * bv.x; acc2[0][1] += a0 * bv.y; acc2[0][2] += a0 * bv.z; acc2[0][3] += a0 * bv.w;
        acc2[1][0] += a1 * bv.x; acc2[1][1] += a1 * bv.y; acc2[1][2] += a1 * bv.z; acc2[1][3] += a1 * bv.w;
        acc2[2][0] += a2 * bv.x; acc2[2][1] += a2 * bv.y; acc2[2][2] += a2 * bv.z; acc2[2][3] += a2 * bv.w;
        acc2[3][0] += a3 * bv.x; acc2[3][1] += a3 * bv.y; acc2[3][2] += a3 * bv.z; acc2[3][3] += a3 * bv.w;
    }

    #pragma unroll
    for (int i = 0; i < 4; i++) {
        const int c = 4 * ty2 + i;
        float4 r4;
        r4.x = acc2[i][0]; r4.y = acc2[i][1]; r4.z = acc2[i][2]; r4.w = acc2[i][3];
        *(float4*)(out + (((size_t)(b * CC + c) * TT + t) * NN) + m0b) = r4;
    }
}

extern "C" void kernel_launch(void* const* d_in, const int* in_sizes, int n_in,
                              void* d_out, int out_size)
{
    const float* x    = (const float*)d_in[0];
    const float* A    = (const float*)d_in[1];
    const float* W    = (const float*)d_in[2];
    const float* bias = (const float*)d_in[3];
    float* out = (float*)d_out;

    const int xout_elems = BB * CC * TT * NN;           // 8,388,608
    const int copyA = (out_size > xout_elems) ? 1 : 0;  // tuple output (x_out, A)

    wt_transpose_kernel<<<16, 256>>>(W);

    cudaFuncSetAttribute(ctg_kernel, cudaFuncAttributeMaxDynamicSharedMemorySize, SMEM_BYTES);
    ctg_kernel<<<BB * TT, 256, SMEM_BYTES>>>(x, A, bias, out, copyA);
}

// round 17
// speedup vs baseline: 1.2189x; 1.2189x over previous
#include <cuda_runtime.h>

// Fixed problem shapes
#define BB 64
#define CC 64   // C == Co
#define TT 32
#define NN 64
#define KK 3

#define STRIDE 68               // 64 + 4 pad
#define BUF (64 * STRIDE)
#define SMEM_FLOATS (2 * BUF + 3 * 64)
#define SMEM_BYTES  (SMEM_FLOATS * 4)     // 35,584 B -> 5 CTAs/SM

// W transposed once into device-global scratch (WT[c][o] = W[o][c])
__device__ float g_WT[CC * CC];

__global__ void wt_transpose_kernel(const float* __restrict__ W)
{
    const int base = blockIdx.x * 1024 + threadIdx.x;
    #pragma unroll
    for (int j = 0; j < 4; j++) {
        const int i = base + j * 256;     // 0..4095
        g_WT[(i & 63) * CC + (i >> 6)] = W[i];
    }
}

// Forced 64-bit shared loads (R6, verified)
#define LDS64(v0, v1, addr) \
    asm("ld.shared.v2.f32 {%0,%1}, [%2];" : "=f"(v0), "=f"(v1) : "r"(addr))

// One CTA per (b, t). 256 threads, 4x4 register tiles, 2 aliased buffers.
// s0: x tile [c][n]  -> Asum [n][m]
// s1: WT tile [c][o] -> yT tile [n][o]
// sD: dinv, 3 slabs of 64 (one per k -> no trailing barrier per k)
__global__ void __launch_bounds__(256, 5)
ctg_kernel(const float* __restrict__ x,
           const float* __restrict__ A,
           const float* __restrict__ bias,
           float* __restrict__ out,
           int copyA)
{
    extern __shared__ float sm[];
    float* s0 = sm;
    float* s1 = sm + BUF;
    float* sD = sm + 2 * BUF;

    const unsigned s0b = (unsigned)__cvta_generic_to_shared(s0);
    const unsigned s1b = (unsigned)__cvta_generic_to_shared(s1);

    const int tid = threadIdx.x;
    const int b   = blockIdx.x / TT;
    const int t   = blockIdx.x % TT;
    const int tx  = tid & 15;   // 4-col group
    const int ty  = tid >> 4;   // 4-row group
    const int m0  = tx * 4;

    // ---- stage x[b,:,t,:] ([c][n]) and WT ([c][o]) via float4 ----
    #pragma unroll
    for (int it = 0; it < 4; it++) {
        const int e4 = it * 256 + tid;    // float4 slot 0..1023
        const int r  = e4 >> 4;
        const int c4 = e4 & 15;
        *(float4*)(s0 + r * STRIDE + c4 * 4) =
            *(const float4*)(x + (((size_t)(b * CC + r) * TT + t) * NN) + c4 * 4);
        *(float4*)(s1 + r * STRIDE + c4 * 4) =
            *(const float4*)(g_WT + (size_t)e4 * 4);
    }
    __syncthreads();

    // ---- GEMM1: yT[n][o] = sum_c x[c][n] * WT[c][o] + bias[o] ----
    float acc[4][4];
    #pragma unroll
    for (int i = 0; i < 4; i++)
        #pragma unroll
        for (int j = 0; j < 4; j++) acc[i][j] = 0.0f;

    #pragma unroll 16
    for (int kk = 0; kk < 64; kk++) {
        const unsigned aaddr = s0b + (unsigned)(kk * STRIDE + ty * 4) * 4u;
        const unsigned baddr = s1b + (unsigned)(kk * STRIDE + tx * 4) * 4u;
        float a0, a1, a2, a3, b0, b1, b2, b3;
        LDS64(a0, a1, aaddr);        // x[kk][4ty..]   (broadcast)
        LDS64(a2, a3, aaddr + 8);
        LDS64(b0, b1, baddr);        // WT[kk][4tx..]  (conflict-free)
        LDS64(b2, b3, baddr + 8);
        acc[0][0] += a0 * b0; acc[0][1] += a0 * b1; acc[0][2] += a0 * b2; acc[0][3] += a0 * b3;
        acc[1][0] += a1 * b0; acc[1][1] += a1 * b1; acc[1][2] += a1 * b2; acc[1][3] += a1 * b3;
        acc[2][0] += a2 * b0; acc[2][1] += a2 * b1; acc[2][2] += a2 * b2; acc[2][3] += a2 * b3;
        acc[3][0] += a3 * b0; acc[3][1] += a3 * b1; acc[3][2] += a3 * b2; acc[3][3] += a3 * b3;
    }
    __syncthreads();   // all x/WT reads done before overwriting s1 with yT

    {
        const float4 bia = *(const float4*)(bias + tx * 4);
        #pragma unroll
        for (int i = 0; i < 4; i++) {
            float4 r4;
            r4.x = acc[i][0] + bia.x;
            r4.y = acc[i][1] + bia.y;
            r4.z = acc[i][2] + bia.z;
            r4.w = acc[i][3] + bia.w;
            *(float4*)(s1 + (4 * ty + i) * STRIDE + tx * 4) = r4;   // yT[n][o]
        }
    }

    // ---- A-phase: register A_k + register Asum, shfl row degrees ----
    float* outA = out + (size_t)BB * CC * TT * NN;

    float4 asum[4];
    #pragma unroll
    for (int it = 0; it < 4; it++) { asum[it].x = asum[it].y = asum[it].z = asum[it].w = 0.0f; }

    #pragma unroll
    for (int k = 0; k < KK; k++) {
        const size_t base = (((size_t)b * KK + k) * TT + t) * (size_t)(NN * NN);
        float* sDk = sD + k * 64;

        float4 a[4];
        #pragma unroll
        for (int it = 0; it < 4; it++) {
            const int e4 = it * 256 + tid;
            a[it] = *(const float4*)(A + base + (size_t)e4 * 4);
            if (copyA) *(float4*)(outA + base + (size_t)e4 * 4) = a[it];
        }

        // row degrees: each half-warp holds one full row (row = it*16 + ty)
        #pragma unroll
        for (int it = 0; it < 4; it++) {
            float s = a[it].x + a[it].y + a[it].z + a[it].w;
            s += __shfl_xor_sync(0xffffffffu, s, 1);
            s += __shfl_xor_sync(0xffffffffu, s, 2);
            s += __shfl_xor_sync(0xffffffffu, s, 4);
            s += __shfl_xor_sync(0xffffffffu, s, 8);
            if (tx == 0) sDk[it * 16 + ty] = rsqrtf(s + 1.0f);   // A_tilde = A + I
        }
        __syncthreads();

        const float4 dm = *(const float4*)(sDk + m0);
        #pragma unroll
        for (int it = 0; it < 4; it++) {
            const int n = it * 16 + ty;
            const float dn = sDk[n];
            float4 v = a[it];
            const int d = n - m0;
            if (d == 0) v.x += 1.0f;
            if (d == 1) v.y += 1.0f;
            if (d == 2) v.z += 1.0f;
            if (d == 3) v.w += 1.0f;
            asum[it].x += v.x * dn * dm.x;
            asum[it].y += v.y * dn * dm.y;
            asum[it].z += v.z * dn * dm.z;
            asum[it].w += v.w * dn * dm.w;
        }
        // no trailing sync: next k writes a different sD slab
    }

    // Asum -> s0 (x is dead since post-GEMM1 barrier)
    #pragma unroll
    for (int it = 0; it < 4; it++)
        *(float4*)(s0 + (it * 16 + ty) * STRIDE + m0) = asum[it];
    __syncthreads();

    // ---- GEMM2: x_out[c][m] = sum_n yT[n][c] * Asum[n][m] ----
    #pragma unroll
    for (int i = 0; i < 4; i++)
        #pragma unroll
        for (int j = 0; j < 4; j++) acc[i][j] = 0.0f;

    #pragma unroll 16
    for (int kk = 0; kk < 64; kk++) {
        const unsigned aaddr = s1b + (unsigned)(kk * STRIDE + ty * 4) * 4u;
        const unsigned baddr = s0b + (unsigned)(kk * STRIDE + tx * 4) * 4u;
        float a0, a1, a2, a3, b0, b1, b2, b3;
        LDS64(a0, a1, aaddr);        // yT[kk][4ty..]   (broadcast)
        LDS64(a2, a3, aaddr + 8);
        LDS64(b0, b1, baddr);        // Asum[kk][4tx..] (conflict-free)
        LDS64(b2, b3, baddr + 8);
        acc[0][0] += a0 * b0; acc[0][1] += a0 * b1; acc[0][2] += a0 * b2; acc[0][3] += a0 * b3;
        acc[1][0] += a1 * b0; acc[1][1] += a1 * b1; acc[1][2] += a1 * b2; acc[1][3] += a1 * b3;
        acc[2][0] += a2 * b0; acc[2][1] += a2 * b1; acc[2][2] += a2 * b2; acc[2][3] += a2 * b3;
        acc[3][0] += a3 * b0; acc[3][1] += a3 * b1; acc[3][2] += a3 * b2; acc[3][3] += a3 * b3;
    }

    #pragma unroll
    for (int i = 0; i < 4; i++) {
        const int c = 4 * ty + i;
        float4 r4;
        r4.x = acc[i][0]; r4.y = acc[i][1]; r4.z = acc[i][2]; r4.w = acc[i][3];
        *(float4*)(out + (((size_t)(b * CC + c) * TT + t) * NN) + m0) = r4;
    }
}

extern "C" void kernel_launch(void* const* d_in, const int* in_sizes, int n_in,
                              void* d_out, int out_size)
{
    const float* x    = (const float*)d_in[0];
    const float* A    = (const float*)d_in[1];
    const float* W    = (const float*)d_in[2];
    const float* bias = (const float*)d_in[3];
    float* out = (float*)d_out;

    const int xout_elems = BB * CC * TT * NN;           // 8,388,608
    const int copyA = (out_size > xout_elems) ? 1 : 0;  // tuple output (x_out, A)

    wt_transpose_kernel<<<4, 256>>>(W);

    cudaFuncSetAttribute(ctg_kernel, cudaFuncAttributeMaxDynamicSharedMemorySize, SMEM_BYTES);
    ctg_kernel<<<BB * TT, 256, SMEM_BYTES>>>(x, A, bias, out, copyA);
}